// round 16
// baseline (speedup 1.0000x reference)
#include <cuda_runtime.h>
#include <cuda_bf16.h>
#include <cstdint>

typedef unsigned long long u64;
typedef unsigned int u32;
typedef __nv_bfloat16 bf16;

// ---------------------------------------------------------------------------
// EnrichAttention. Pre-split bf16x3 HMMA GEMMs (cp.async pipeline) -> softmax
// -> ctx -> xp -> GRU v6: two interleaved batch-pair recurrences per CTA
// (v4 step structure, latency hidden behind the sibling pair's compute).
// ---------------------------------------------------------------------------

// fp32 scratch: MM [32][512][512] at 0; XP [16384][768] at 8388608
#define F_MM 0
#define F_XP 8388608
__device__ float g_f32[20971520];

// bf16 scratch offsets (elements)
#define O_GGH   0
#define O_GGL   8388608
#define O_X2H   16777216
#define O_X2L   20971520
#define O_X2TH  25165824
#define O_X2TL  29360128
#define O_T1H   33554432
#define O_T1L   37748736
#define O_A1H   41943040
#define O_A1L   46137344
#define O_A2H   50331648
#define O_A2L   54525952
#define O_MH    58720256
#define O_ML    67108864
#define O_W1H   75497472
#define O_W1L   75563008
#define O_W2H   75628544
#define O_W2L   75694080
#define O_DTH   75759616
#define O_DTL   75825152
#define O_WIHH  75890688
#define O_WIHL  76283904
__device__ bf16 g_bf[76677120];

// ---- helpers ----------------------------------------------------------------
__device__ __forceinline__ u32 saddr(const void* p) {
    u32 a;
    asm("{ .reg .u64 t; cvta.to.shared.u64 t, %1; cvt.u32.u64 %0, t; }"
        : "=r"(a) : "l"(p));
    return a;
}
__device__ __forceinline__ void mbar_wait(u32 mbar, u32 parity) {
    u32 done;
    asm volatile(
        "{\n\t.reg .pred p;\n\t"
        "mbarrier.try_wait.parity.acquire.cta.shared::cta.b64 p, [%1], %2;\n\t"
        "selp.b32 %0, 1, 0, p;\n\t}"
        : "=r"(done) : "r"(mbar), "r"(parity) : "memory");
    if (!done) {
        asm volatile(
            "{\n\t.reg .pred P1;\n\t"
            "WL%=:\n\t"
            "mbarrier.try_wait.parity.acquire.cta.shared::cta.b64 P1, [%0], %1, 0x989680;\n\t"
            "@P1 bra.uni WD%=;\n\t"
            "bra.uni WL%=;\n\t"
            "WD%=:\n\t}"
            :: "r"(mbar), "r"(parity) : "memory");
    }
}
__device__ __forceinline__ void cp16(u32 smem, const void* g) {
    asm volatile("cp.async.cg.shared.global [%0], [%1], 16;"
                 :: "r"(smem), "l"(g) : "memory");
}
__device__ __forceinline__ void split1(float v, bf16& h, bf16& l) {
    h = __float2bfloat16_rn(v);
    l = __float2bfloat16_rn(v - __bfloat162float(h));
}

// ---------------------------------------------------------------------------
// Conversion kernels (unchanged from R15)
// ---------------------------------------------------------------------------
__global__ void conv_split(const float* __restrict__ src,
                           bf16* __restrict__ dh, bf16* __restrict__ dl,
                           int src_ld, int dst_ld, int shift, int total)
{
    const int idx = blockIdx.x * 256 + threadIdx.x;
    if (idx >= total) return;
    const int row = idx >> shift;
    const int c4 = (idx & ((1 << shift) - 1)) << 2;
    float4 v = *(const float4*)(src + (size_t)row * src_ld + c4);
    bf16 h0, l0, h1, l1, h2, l2, h3, l3;
    split1(v.x, h0, l0); split1(v.y, h1, l1);
    split1(v.z, h2, l2); split1(v.w, h3, l3);
    u32 hA = ((u32)__bfloat16_as_ushort(h1) << 16) | __bfloat16_as_ushort(h0);
    u32 hB = ((u32)__bfloat16_as_ushort(h3) << 16) | __bfloat16_as_ushort(h2);
    u32 lA = ((u32)__bfloat16_as_ushort(l1) << 16) | __bfloat16_as_ushort(l0);
    u32 lB = ((u32)__bfloat16_as_ushort(l3) << 16) | __bfloat16_as_ushort(l2);
    *(uint2*)(dh + (size_t)row * dst_ld + c4) = make_uint2(hA, hB);
    *(uint2*)(dl + (size_t)row * dst_ld + c4) = make_uint2(lA, lB);
}

__global__ void conv_trans(const float* __restrict__ src,
                           bf16* __restrict__ dh, bf16* __restrict__ dl,
                           int R, int C, long long ss, long long sd)
{
    __shared__ float t[32][33];
    const int z = blockIdx.z;
    src += (size_t)z * ss; dh += (size_t)z * sd; dl += (size_t)z * sd;
    const int c0 = blockIdx.x * 32, r0 = blockIdx.y * 32;
    const int tx = threadIdx.x, ty = threadIdx.y;
#pragma unroll
    for (int i = 0; i < 4; i++)
        t[ty + i * 8][tx] = src[(size_t)(r0 + ty + i * 8) * C + c0 + tx];
    __syncthreads();
#pragma unroll
    for (int i = 0; i < 4; i++) {
        const float v = t[tx][ty + i * 8];
        bf16 h, l; split1(v, h, l);
        const size_t o = (size_t)(c0 + ty + i * 8) * R + r0 + tx;
        dh[o] = h; dl[o] = l;
    }
}

// ---------------------------------------------------------------------------
// bf16x3 HMMA GEMM, pre-split operands, 4-stage cp.async pipeline (R15).
// ---------------------------------------------------------------------------
#define LDR 40
#define MATB 10240
#define STGB (4 * MATB)
#define GEMM_SMEM (4 * STGB)

__device__ __forceinline__ void ldsm4(u32& r0, u32& r1, u32& r2, u32& r3, u32 a) {
    asm volatile("ldmatrix.sync.aligned.m8n8.x4.shared.b16 {%0,%1,%2,%3}, [%4];"
                 : "=r"(r0), "=r"(r1), "=r"(r2), "=r"(r3) : "r"(a));
}
__device__ __forceinline__ void mma_bf16(float* c, const u32* a, const u32* b) {
    asm volatile(
        "mma.sync.aligned.m16n8k16.row.col.f32.bf16.bf16.f32 "
        "{%0,%1,%2,%3}, {%4,%5,%6,%7}, {%8,%9}, {%0,%1,%2,%3};"
        : "+f"(c[0]), "+f"(c[1]), "+f"(c[2]), "+f"(c[3])
        : "r"(a[0]), "r"(a[1]), "r"(a[2]), "r"(a[3]), "r"(b[0]), "r"(b[1]));
}

template<int EPI, int OUT>
__global__ void __launch_bounds__(512) gemm_bb(
    const bf16* __restrict__ Ah, const bf16* __restrict__ Al,
    const bf16* __restrict__ Bh, const bf16* __restrict__ Bl,
    float* __restrict__ C, bf16* __restrict__ Ch, bf16* __restrict__ Cl,
    int K, int lda, int ldb, int ldc,
    long long sA, long long sB, long long sC,
    const float* __restrict__ E, int eN)
{
    extern __shared__ __align__(16) unsigned char sm[];
    const long long z = blockIdx.z;
    Ah += z * sA; Al += z * sA;
    Bh += z * sB; Bl += z * sB;
    if (OUT == 0) C += z * sC; else { Ch += z * sC; Cl += z * sC; }

    const int tid = threadIdx.x;
    const int wid = tid >> 5, lane = tid & 31;
    const int wm = wid >> 2, wn = wid & 3;
    const int m0 = blockIdx.y * 128, n0 = blockIdx.x * 128;

    const int row = tid >> 2;
    const int ko = (tid & 3) * 8;
    const u32 smb = saddr(sm);
    const u32 sdst = smb + (u32)(row * LDR + ko) * 2;

    const int q = lane >> 3, lr = lane & 7;
    const int a_t = (lr + (q & 1) * 8) * LDR + (q >> 1) * 8;
    const int b_t = (lr + (q >> 1) * 8) * LDR + (q & 1) * 8;

    float acc[2][4][4];
#pragma unroll
    for (int mt = 0; mt < 2; mt++)
#pragma unroll
        for (int nt = 0; nt < 4; nt++)
#pragma unroll
            for (int e = 0; e < 4; e++) acc[mt][nt][e] = 0.f;

    const int nch = K >> 5;

#define ISSUE(c, st) do {                                                    \
        const u32 sb_ = sdst + (u32)(st) * STGB;                             \
        const size_t ao_ = (size_t)(m0 + row) * lda + (c) * 32 + ko;         \
        const size_t bo_ = (size_t)(n0 + row) * ldb + (c) * 32 + ko;         \
        cp16(sb_,             Ah + ao_);                                     \
        cp16(sb_ + MATB,      Al + ao_);                                     \
        cp16(sb_ + 2 * MATB,  Bh + bo_);                                     \
        cp16(sb_ + 3 * MATB,  Bl + bo_);                                     \
        asm volatile("cp.async.commit_group;" ::: "memory");                 \
    } while (0)

    ISSUE(0, 0); ISSUE(1, 1); ISSUE(2, 2);

    for (int c = 0; c < nch; c++) {
        asm volatile("cp.async.wait_group 2;" ::: "memory");
        __syncthreads();
        if (c + 3 < nch) ISSUE(c + 3, (c + 3) & 3);

        const u32 base = smb + (u32)(c & 3) * STGB;
#pragma unroll
        for (int ks = 0; ks < 32; ks += 16) {
            u32 ah[2][4], al[2][4], bh[4][2], bl[4][2];
#pragma unroll
            for (int mt = 0; mt < 2; mt++) {
                const u32 off = (u32)(a_t + (wm * 32 + mt * 16) * LDR + ks) * 2;
                ldsm4(ah[mt][0], ah[mt][1], ah[mt][2], ah[mt][3], base + off);
                ldsm4(al[mt][0], al[mt][1], al[mt][2], al[mt][3], base + off + MATB);
            }
#pragma unroll
            for (int np = 0; np < 2; np++) {
                const u32 off = (u32)(b_t + (wn * 32 + np * 16) * LDR + ks) * 2;
                u32 t0, t1, t2, t3;
                ldsm4(t0, t1, t2, t3, base + off + 2 * MATB);
                bh[2 * np][0] = t0; bh[2 * np][1] = t1;
                bh[2 * np + 1][0] = t2; bh[2 * np + 1][1] = t3;
                ldsm4(t0, t1, t2, t3, base + off + 3 * MATB);
                bl[2 * np][0] = t0; bl[2 * np][1] = t1;
                bl[2 * np + 1][0] = t2; bl[2 * np + 1][1] = t3;
            }
#pragma unroll
            for (int mt = 0; mt < 2; mt++)
#pragma unroll
                for (int nt = 0; nt < 4; nt++) {
                    mma_bf16(acc[mt][nt], ah[mt], bh[nt]);
                    mma_bf16(acc[mt][nt], ah[mt], bl[nt]);
                    mma_bf16(acc[mt][nt], al[mt], bh[nt]);
                }
        }
    }
#undef ISSUE

    const int rbase = m0 + wm * 32 + (lane >> 2);
    const int cbase = n0 + wn * 32 + (lane & 3) * 2;
#pragma unroll
    for (int mt = 0; mt < 2; mt++) {
#pragma unroll
        for (int nt = 0; nt < 4; nt++) {
            const int col = cbase + nt * 8;
#pragma unroll
            for (int half = 0; half < 2; half++) {
                const int r = rbase + mt * 16 + half * 8;
                float v0 = acc[mt][nt][half * 2];
                float v1 = acc[mt][nt][half * 2 + 1];
                if (EPI == 1) { v0 = fmaxf(v0, 0.f); v1 = fmaxf(v1, 0.f); }
                else if (EPI == 2) {
                    const float2 e = *(const float2*)&E[(size_t)r * eN + col];
                    v0 *= e.x; v1 *= e.y;
                } else if (EPI == 3) {
                    const float2 e = *(const float2*)&E[col];
                    v0 += e.x; v1 += e.y;
                }
                if (OUT == 0) {
                    *(float2*)&C[(size_t)r * ldc + col] = make_float2(v0, v1);
                } else {
                    bf16 h0, l0, h1, l1;
                    split1(v0, h0, l0); split1(v1, h1, l1);
                    *(u32*)&Ch[(size_t)r * ldc + col] =
                        ((u32)__bfloat16_as_ushort(h1) << 16) | __bfloat16_as_ushort(h0);
                    *(u32*)&Cl[(size_t)r * ldc + col] =
                        ((u32)__bfloat16_as_ushort(l1) << 16) | __bfloat16_as_ushort(l0);
                }
            }
        }
    }
}

// ---------------------------------------------------------------------------
__global__ void softmax_dim1_kernel(const float* __restrict__ Mm,
                                    bf16* __restrict__ mh, bf16* __restrict__ ml)
{
    const int idx = blockIdx.x * 256 + threadIdx.x;
    const int b = idx >> 9, c = idx & 511;
    const float* p = Mm + (size_t)b * (512 * 512) + c;

    float mx = -1e30f, s = 0.f;
    for (int i = 0; i < 512; i++) {
        const float v = p[(size_t)i * 512];
        const float nm = fmaxf(mx, v);
        s = s * __expf(mx - nm) + __expf(v - nm);
        mx = nm;
    }
    const float inv = 1.f / s;
    bf16* ph = mh + (size_t)b * (512 * 512) + c;
    bf16* pl = ml + (size_t)b * (512 * 512) + c;
    for (int i = 0; i < 512; i++) {
        const float v = __expf(p[(size_t)i * 512] - mx) * inv;
        bf16 h, l; split1(v, h, l);
        ph[(size_t)i * 512] = h;
        pl[(size_t)i * 512] = l;
    }
}

// ---------------------------------------------------------------------------
// GRU v6: 8 clusters x 8 CTAs x 256 thr; each CTA interleaves TWO independent
// batch-pair recurrences (A, B) with the exact v4 step structure. While pair
// A's st.async credits are in flight, the CTA computes pair B's step — the
// DSMEM+wake latency is hidden behind the sibling pair's compute.
// smem layout: hbufA[2][2][128] | hbufB (same, +4096B) | partsA | partsB |
// mbars[4] = {A0, A1, B0, B1}.
// ---------------------------------------------------------------------------
__device__ __forceinline__ u64 pk2(float a, float b) {
    u64 r; asm("mov.b64 %0, {%1, %2};" : "=l"(r) : "f"(a), "f"(b)); return r;
}
__device__ __forceinline__ void fma2(u64& d, u64 a, u64 b) {
    asm("fma.rn.f32x2 %0, %1, %2, %0;" : "+l"(d) : "l"(a), "l"(b));
}
__device__ __forceinline__ u64 add2(u64 a, u64 b) {
    u64 d; asm("add.rn.f32x2 %0, %1, %2;" : "=l"(d) : "l"(a), "l"(b)); return d;
}
__device__ __forceinline__ float2 unpk(u64 v) {
    float2 f; asm("mov.b64 {%0, %1}, %2;" : "=f"(f.x), "=f"(f.y) : "l"(v)); return f;
}

// One pair-step. CUR = consumed h buffer (t&1). doff/moff select the DSMEM
// destination (buffer CUR^1 of this pair) relative to the pair-A/buf-0 base
// addresses in dd/dm.
template<int CUR, bool DO_WAIT>
__device__ __forceinline__ void gstep(
    int t, int tid, int kq, int b0p, int gi, int b_l, int hl2,
    const u64 (&w2reg)[3][16],
    const u64* __restrict__ hbuf,      // pair base: [2][2][128]
    u64* __restrict__ parts,           // pair parts: [3][2][8][32]
    u32 mb_cur, u32 parity,
    const u32 (&dd)[8], const u32 (&dm)[8], u32 doff, u32 moff,
    float br, float bz, float bn,
    float& xr_c, float& xz_c, float& xn_c,
    const float* __restrict__ xp, float* __restrict__ out)
{
    float xr_n = 0.f, xz_n = 0.f, xn_n = 0.f;
    if (tid < 64) {
        const int tn = (t + 1 < 512) ? t + 1 : 511;
        const float* p = xp + ((size_t)(b0p + b_l) * 512 + tn) * 768 + gi * 32 + hl2;
        xr_n = __ldg(p); xz_n = __ldg(p + 256); xn_n = __ldg(p + 512);
    }

    if (DO_WAIT) {
        mbar_wait(mb_cur, parity);
        if (tid == 0)
            asm volatile("mbarrier.arrive.expect_tx.shared.b64 _, [%0], %1;"
                         :: "r"(mb_cur), "r"(2048u) : "memory");
    }

    const int h_l = tid & 31;
    const u64* h0p = hbuf + CUR * 256 + kq * 16;
    const u64* h1p = hbuf + CUR * 256 + 128 + kq * 16;
    u64 a00 = 0, a01 = 0, a10 = 0, a11 = 0, a20 = 0, a21 = 0;
#pragma unroll
    for (int kp = 0; kp < 16; kp++) {
        const u64 ha = h0p[kp], hb = h1p[kp];
        fma2(a00, ha, w2reg[0][kp]); fma2(a01, hb, w2reg[0][kp]);
        fma2(a10, ha, w2reg[1][kp]); fma2(a11, hb, w2reg[1][kp]);
        fma2(a20, ha, w2reg[2][kp]); fma2(a21, hb, w2reg[2][kp]);
    }
    parts[((0 * 2 + 0) * 8 + kq) * 32 + h_l] = a00;
    parts[((0 * 2 + 1) * 8 + kq) * 32 + h_l] = a01;
    parts[((1 * 2 + 0) * 8 + kq) * 32 + h_l] = a10;
    parts[((1 * 2 + 1) * 8 + kq) * 32 + h_l] = a11;
    parts[((2 * 2 + 0) * 8 + kq) * 32 + h_l] = a20;
    parts[((2 * 2 + 1) * 8 + kq) * 32 + h_l] = a21;
    __syncthreads();

    if (tid < 64) {
        u64 sr = parts[((0 * 2 + b_l) * 8 + 0) * 32 + hl2];
        u64 sz = parts[((1 * 2 + b_l) * 8 + 0) * 32 + hl2];
        u64 sn = parts[((2 * 2 + b_l) * 8 + 0) * 32 + hl2];
#pragma unroll
        for (int qq = 1; qq < 8; qq++) {
            sr = add2(sr, parts[((0 * 2 + b_l) * 8 + qq) * 32 + hl2]);
            sz = add2(sz, parts[((1 * 2 + b_l) * 8 + qq) * 32 + hl2]);
            sn = add2(sn, parts[((2 * 2 + b_l) * 8 + qq) * 32 + hl2]);
        }
        const float2 fr = unpk(sr), fz = unpk(sz), fn = unpk(sn);
        const float hr = fr.x + fr.y + br;
        const float hz = fz.x + fz.y + bz;
        const float hn = fn.x + fn.y + bn;

        const float r = 1.f / (1.f + __expf(-(xr_c + hr)));
        const float z = 1.f / (1.f + __expf(-(xz_c + hz)));
        const float n = tanhf(xn_c + r * hn);
        const float hp = ((const float*)(hbuf + CUR * 256 + b_l * 128))[gi * 32 + hl2];
        const float hnew = (1.f - z) * n + z * hp;
        const u32 hbits = __float_as_uint(hnew);

#pragma unroll
        for (int rk = 0; rk < 8; rk++)
            asm volatile(
                "st.async.shared::cluster.mbarrier::complete_tx::bytes.b32 [%0], %1, [%2];"
                :: "r"(dd[rk] + doff), "r"(hbits), "r"(dm[rk] + moff) : "memory");

        out[((size_t)(b0p + b_l) * 512 + t) * 256 + gi * 32 + hl2] = hnew;
    }
    xr_c = xr_n; xz_c = xz_n; xn_c = xn_n;
}

__global__ void __launch_bounds__(256, 1) __cluster_dims__(8, 1, 1)
gru_kernel(const float* __restrict__ xp,
           const float* __restrict__ whh,
           const float* __restrict__ bhh,
           float* __restrict__ out)
{
    // Contiguous layout so pair-B addresses are pair-A + constant offsets.
    __shared__ __align__(16) u64 hbufA[2][2][128];   // 4096 B
    __shared__ __align__(16) u64 hbufB[2][2][128];   // +4096
    __shared__ __align__(16) u64 partsA[3 * 2 * 8 * 32];
    __shared__ __align__(16) u64 partsB[3 * 2 * 8 * 32];
    __shared__ __align__(8)  u64 mbars[4];           // A0, A1, B0, B1

    const int tid = threadIdx.x;
    u32 gi; asm("mov.u32 %0, %%cluster_ctarank;" : "=r"(gi));
    const int b0A = (blockIdx.x >> 3) * 4;
    const int b0B = b0A + 2;
    const int h_l = tid & 31;
    const int kq  = tid >> 5;
    const int hg  = gi * 32 + h_l;

    // weights shared by both pairs (same as v4: 48 u64/thread)
    u64 w2reg[3][16];
#pragma unroll
    for (int g = 0; g < 3; g++) {
        const float* wr = whh + (size_t)(g * 256 + hg) * 256 + kq * 32;
#pragma unroll
        for (int kp = 0; kp < 16; kp += 2) {
            float4 v = __ldg((const float4*)(wr + kp * 2));
            w2reg[g][kp]     = pk2(v.x, v.y);
            w2reg[g][kp + 1] = pk2(v.z, v.w);
        }
    }

    const u32 mbA0 = saddr(&mbars[0]);
    if (tid == 0) {
#pragma unroll
        for (int i = 0; i < 4; i++)
            asm volatile("mbarrier.init.shared.b64 [%0], 1;"
                         :: "r"(mbA0 + i * 8) : "memory");
        asm volatile("fence.proxy.async.shared::cta;" ::: "memory");
#pragma unroll
        for (int i = 0; i < 4; i++)
            asm volatile("mbarrier.arrive.expect_tx.shared.b64 _, [%0], %1;"
                         :: "r"(mbA0 + i * 8), "r"(2048u) : "memory");
    }
    // zero all h buffers (8192 B = 1024 u64)
    ((u64*)hbufA)[tid]       = 0ull;
    ((u64*)hbufA)[tid + 256] = 0ull;
    ((u64*)hbufB)[tid]       = 0ull;
    ((u64*)hbufB)[tid + 256] = 0ull;
    __syncthreads();
    asm volatile("barrier.cluster.arrive.aligned;" ::: "memory");
    asm volatile("barrier.cluster.wait.aligned;" ::: "memory");

    // finalize-thread state
    float brA = 0.f, bzA = 0.f, bnA = 0.f;
    int b_l = 0, hl2 = 0;
    u32 dd[8], dm[8];
#pragma unroll
    for (int rk = 0; rk < 8; rk++) { dd[rk] = 0u; dm[rk] = 0u; }
    if (tid < 64) {
        b_l = tid >> 5; hl2 = tid & 31;
        const int hgf = gi * 32 + hl2;
        brA = __ldg(&bhh[hgf]);
        bzA = __ldg(&bhh[256 + hgf]);
        bnA = __ldg(&bhh[512 + hgf]);
        // base: pair A, buffer 0 slot address
        const u32 la0 = saddr(&((float*)&hbufA[0][b_l][0])[hgf]);
#pragma unroll
        for (int rk = 0; rk < 8; rk++) {
            asm("mapa.shared::cluster.u32 %0, %1, %2;" : "=r"(dd[rk]) : "r"(la0), "r"(rk));
            asm("mapa.shared::cluster.u32 %0, %1, %2;" : "=r"(dm[rk]) : "r"(mbA0), "r"(rk));
        }
    }
    // offsets: buffer 1 = +2048B data / +8B mbar; pair B = +4096B / +16B
    const u32 D1 = 2048u, MB1 = 8u, DB = 4096u, MBB = 16u;

    // xp(0) for both pairs
    float xA[3] = {0.f, 0.f, 0.f}, xB[3] = {0.f, 0.f, 0.f};
    if (tid < 64) {
        const float* pA = xp + ((size_t)(b0A + b_l) * 512) * 768 + gi * 32 + hl2;
        const float* pB = xp + ((size_t)(b0B + b_l) * 512) * 768 + gi * 32 + hl2;
        xA[0] = __ldg(pA); xA[1] = __ldg(pA + 256); xA[2] = __ldg(pA + 512);
        xB[0] = __ldg(pB); xB[1] = __ldg(pB + 256); xB[2] = __ldg(pB + 512);
    }

    u32 pA0 = 0, pA1 = 0, pB0 = 0, pB1 = 0;
    // t=0: both pairs consume local zeros; write h(1) -> buf1 (credits mb*1)
    gstep<0, false>(0, tid, kq, b0A, gi, b_l, hl2, w2reg, (const u64*)hbufA,
                    partsA, 0u, 0u, dd, dm, D1, MB1,
                    brA, bzA, bnA, xA[0], xA[1], xA[2], xp, out);
    gstep<0, false>(0, tid, kq, b0B, gi, b_l, hl2, w2reg, (const u64*)hbufB,
                    partsB, 0u, 0u, dd, dm, D1 + DB, MB1 + MBB,
                    brA, bzA, bnA, xB[0], xB[1], xB[2], xp, out);
    for (int t = 1; t < 511; t += 2) {
        // odd t: consume buf1 (mb*1), write buf0
        gstep<1, true>(t, tid, kq, b0A, gi, b_l, hl2, w2reg, (const u64*)hbufA,
                       partsA, mbA0 + MB1, pA1, dd, dm, 0u, 0u,
                       brA, bzA, bnA, xA[0], xA[1], xA[2], xp, out);
        pA1 ^= 1u;
        gstep<1, true>(t, tid, kq, b0B, gi, b_l, hl2, w2reg, (const u64*)hbufB,
                       partsB, mbA0 + MB1 + MBB, pB1, dd, dm, DB, MBB,
                       brA, bzA, bnA, xB[0], xB[1], xB[2], xp, out);
        pB1 ^= 1u;
        // even t+1: consume buf0 (mb*0), write buf1
        gstep<0, true>(t + 1, tid, kq, b0A, gi, b_l, hl2, w2reg, (const u64*)hbufA,
                       partsA, mbA0, pA0, dd, dm, D1, MB1,
                       brA, bzA, bnA, xA[0], xA[1], xA[2], xp, out);
        pA0 ^= 1u;
        gstep<0, true>(t + 1, tid, kq, b0B, gi, b_l, hl2, w2reg, (const u64*)hbufB,
                       partsB, mbA0 + MBB, pB0, dd, dm, D1 + DB, MB1 + MBB,
                       brA, bzA, bnA, xB[0], xB[1], xB[2], xp, out);
        pB0 ^= 1u;
    }
    gstep<1, true>(511, tid, kq, b0A, gi, b_l, hl2, w2reg, (const u64*)hbufA,
                   partsA, mbA0 + MB1, pA1, dd, dm, 0u, 0u,
                   brA, bzA, bnA, xA[0], xA[1], xA[2], xp, out);
    gstep<1, true>(511, tid, kq, b0B, gi, b_l, hl2, w2reg, (const u64*)hbufB,
                   partsB, mbA0 + MB1 + MBB, pB1, dd, dm, DB, MBB,
                   brA, bzA, bnA, xB[0], xB[1], xB[2], xp, out);
    // drain: absorb h(512) credits into buf0 barriers of both pairs
    mbar_wait(mbA0, pA0);
    mbar_wait(mbA0 + MBB, pB0);
}

// ---------------------------------------------------------------------------
extern "C" void kernel_launch(void* const* d_in, const int* in_sizes, int n_in,
                              void* d_out, int out_size)
{
    const float* x1  = (const float*)d_in[0];
    const float* x2  = (const float*)d_in[1];
    const float* w1  = (const float*)d_in[2];
    const float* w2  = (const float*)d_in[3];
    const float* Dm  = (const float*)d_in[4];
    const float* Wm  = (const float*)d_in[5];
    const float* wih = (const float*)d_in[6];
    const float* whh = (const float*)d_in[7];
    const float* bih = (const float*)d_in[8];
    const float* bhh = (const float*)d_in[9];
    float* out = (float*)d_out;

    float* f32 = nullptr; bf16* bf = nullptr;
    cudaGetSymbolAddress((void**)&f32, g_f32);
    cudaGetSymbolAddress((void**)&bf, g_bf);

    float* MM = f32 + F_MM;
    float* XP = f32 + F_XP;

    cudaFuncSetAttribute(gemm_bb<1, 1>, cudaFuncAttributeMaxDynamicSharedMemorySize, GEMM_SMEM);
    cudaFuncSetAttribute(gemm_bb<0, 1>, cudaFuncAttributeMaxDynamicSharedMemorySize, GEMM_SMEM);
    cudaFuncSetAttribute(gemm_bb<2, 0>, cudaFuncAttributeMaxDynamicSharedMemorySize, GEMM_SMEM);
    cudaFuncSetAttribute(gemm_bb<3, 0>, cudaFuncAttributeMaxDynamicSharedMemorySize, GEMM_SMEM);

    // ---- conversions ----
    conv_split<<<4096, 256>>>(x1, bf + O_GGH, bf + O_GGL, 256, 512, 6, 16384 * 64);
    conv_split<<<4096, 256>>>(x2, bf + O_X2H, bf + O_X2L, 256, 256, 6, 16384 * 64);
    conv_split<<<64, 256>>>(w1, bf + O_W1H, bf + O_W1L, 256, 256, 6, 256 * 64);
    conv_split<<<64, 256>>>(w2, bf + O_W2H, bf + O_W2L, 256, 256, 6, 256 * 64);
    conv_split<<<384, 256>>>(wih, bf + O_WIHH, bf + O_WIHL, 512, 512, 7, 768 * 128);
    conv_trans<<<dim3(8, 8, 1), dim3(32, 8)>>>(Dm, bf + O_DTH, bf + O_DTL,
                                               256, 256, 0, 0);
    conv_trans<<<dim3(8, 16, 32), dim3(32, 8)>>>(x2, bf + O_X2TH, bf + O_X2TL,
                                                 512, 256,
                                                 (long long)512 * 256,
                                                 (long long)256 * 512);

    // ---- GEMMs ----
    gemm_bb<1, 1><<<dim3(2, 128, 1), 512, GEMM_SMEM>>>(
        bf + O_GGH, bf + O_GGL, bf + O_W1H, bf + O_W1L,
        nullptr, bf + O_T1H, bf + O_T1L,
        256, 512, 256, 256, 0, 0, 0, nullptr, 0);
    gemm_bb<1, 1><<<dim3(2, 128, 1), 512, GEMM_SMEM>>>(
        bf + O_X2H, bf + O_X2L, bf + O_W2H, bf + O_W2L,
        nullptr, bf + O_A2H, bf + O_A2L,
        256, 256, 256, 256, 0, 0, 0, nullptr, 0);
    gemm_bb<0, 1><<<dim3(2, 128, 1), 512, GEMM_SMEM>>>(
        bf + O_T1H, bf + O_T1L, bf + O_DTH, bf + O_DTL,
        nullptr, bf + O_A1H, bf + O_A1L,
        256, 256, 256, 256, 0, 0, 0, nullptr, 0);
    gemm_bb<2, 0><<<dim3(4, 4, 32), 512, GEMM_SMEM>>>(
        bf + O_A1H, bf + O_A1L, bf + O_A2H, bf + O_A2L,
        MM, nullptr, nullptr,
        256, 256, 256, 512,
        (long long)512 * 256, (long long)512 * 256, (long long)512 * 512, Wm, 512);
    softmax_dim1_kernel<<<64, 256>>>(MM, bf + O_MH, bf + O_ML);
    gemm_bb<0, 1><<<dim3(2, 4, 32), 512, GEMM_SMEM>>>(
        bf + O_MH, bf + O_ML, bf + O_X2TH, bf + O_X2TL,
        nullptr, bf + O_GGH + 256, bf + O_GGL + 256,
        512, 512, 512, 512,
        (long long)512 * 512, (long long)256 * 512, (long long)512 * 512,
        nullptr, 0);
    gemm_bb<3, 0><<<dim3(6, 128, 1), 512, GEMM_SMEM>>>(
        bf + O_GGH, bf + O_GGL, bf + O_WIHH, bf + O_WIHL,
        XP, nullptr, nullptr,
        512, 512, 512, 768, 0, 0, 0, bih, 0);
    // GRU v6: 8 clusters x 8 CTAs, two interleaved pairs per CTA
    gru_kernel<<<64, 256>>>(XP, whh, bhh, out);
}

// round 17
// speedup vs baseline: 1.0222x; 1.0222x over previous
#include <cuda_runtime.h>
#include <cuda_bf16.h>
#include <cstdint>

typedef unsigned long long u64;
typedef unsigned int u32;
typedef __nv_bfloat16 bf16;

// ---------------------------------------------------------------------------
// EnrichAttention. Pre-split bf16x3 HMMA GEMMs, 64x128 CTA tile @ 2 CTAs/SM,
// 3-stage cp.async pipeline. Merged conversion kernels. GRU v4 (frozen).
// ---------------------------------------------------------------------------

#define F_MM 0
#define F_XP 8388608
__device__ float g_f32[20971520];

// bf16 scratch offsets (elements)
#define O_GGH   0
#define O_GGL   8388608
#define O_X2H   16777216
#define O_X2L   20971520
#define O_X2TH  25165824
#define O_X2TL  29360128
#define O_T1H   33554432
#define O_T1L   37748736
#define O_A1H   41943040
#define O_A1L   46137344
#define O_A2H   50331648
#define O_A2L   54525952
#define O_MH    58720256
#define O_ML    67108864
#define O_W1H   75497472
#define O_W1L   75563008
#define O_W2H   75628544
#define O_W2L   75694080
#define O_DTH   75759616
#define O_DTL   75825152
#define O_WIHH  75890688
#define O_WIHL  76283904
__device__ bf16 g_bf[76677120];

// ---- helpers ----------------------------------------------------------------
__device__ __forceinline__ u32 saddr(const void* p) {
    u32 a;
    asm("{ .reg .u64 t; cvta.to.shared.u64 t, %1; cvt.u32.u64 %0, t; }"
        : "=r"(a) : "l"(p));
    return a;
}
__device__ __forceinline__ void mbar_wait(u32 mbar, u32 parity) {
    u32 done;
    asm volatile(
        "{\n\t.reg .pred p;\n\t"
        "mbarrier.try_wait.parity.acquire.cta.shared::cta.b64 p, [%1], %2;\n\t"
        "selp.b32 %0, 1, 0, p;\n\t}"
        : "=r"(done) : "r"(mbar), "r"(parity) : "memory");
    if (!done) {
        asm volatile(
            "{\n\t.reg .pred P1;\n\t"
            "WL%=:\n\t"
            "mbarrier.try_wait.parity.acquire.cta.shared::cta.b64 P1, [%0], %1, 0x989680;\n\t"
            "@P1 bra.uni WD%=;\n\t"
            "bra.uni WL%=;\n\t"
            "WD%=:\n\t}"
            :: "r"(mbar), "r"(parity) : "memory");
    }
}
__device__ __forceinline__ void cp16(u32 smem, const void* g) {
    asm volatile("cp.async.cg.shared.global [%0], [%1], 16;"
                 :: "r"(smem), "l"(g) : "memory");
}
__device__ __forceinline__ void split1(float v, bf16& h, bf16& l) {
    h = __float2bfloat16_rn(v);
    l = __float2bfloat16_rn(v - __bfloat162float(h));
}

// ---------------------------------------------------------------------------
// Merged conversion kernels
// ---------------------------------------------------------------------------
// 5 split jobs selected by blockIdx.y: 0:x1->GG, 1:x2->X2, 2:w1, 3:w2, 4:wih
__global__ void conv_split_all(const float* __restrict__ x1,
                               const float* __restrict__ x2,
                               const float* __restrict__ w1,
                               const float* __restrict__ w2,
                               const float* __restrict__ wih,
                               bf16* __restrict__ bfb)
{
    const int job = blockIdx.y;
    const float* src; bf16 *dh, *dl;
    int src_ld, dst_ld, shift, total;
    switch (job) {
        case 0: src = x1;  dh = bfb + O_GGH;  dl = bfb + O_GGL;
                src_ld = 256; dst_ld = 512; shift = 6; total = 1048576; break;
        case 1: src = x2;  dh = bfb + O_X2H;  dl = bfb + O_X2L;
                src_ld = 256; dst_ld = 256; shift = 6; total = 1048576; break;
        case 2: src = w1;  dh = bfb + O_W1H;  dl = bfb + O_W1L;
                src_ld = 256; dst_ld = 256; shift = 6; total = 16384; break;
        case 3: src = w2;  dh = bfb + O_W2H;  dl = bfb + O_W2L;
                src_ld = 256; dst_ld = 256; shift = 6; total = 16384; break;
        default: src = wih; dh = bfb + O_WIHH; dl = bfb + O_WIHL;
                src_ld = 512; dst_ld = 512; shift = 7; total = 98304; break;
    }
    const int idx = blockIdx.x * 256 + threadIdx.x;
    if (idx >= total) return;
    const int row = idx >> shift;
    const int c4 = (idx & ((1 << shift) - 1)) << 2;
    float4 v = *(const float4*)(src + (size_t)row * src_ld + c4);
    bf16 h0, l0, h1, l1, h2, l2, h3, l3;
    split1(v.x, h0, l0); split1(v.y, h1, l1);
    split1(v.z, h2, l2); split1(v.w, h3, l3);
    u32 hA = ((u32)__bfloat16_as_ushort(h1) << 16) | __bfloat16_as_ushort(h0);
    u32 hB = ((u32)__bfloat16_as_ushort(h3) << 16) | __bfloat16_as_ushort(h2);
    u32 lA = ((u32)__bfloat16_as_ushort(l1) << 16) | __bfloat16_as_ushort(l0);
    u32 lB = ((u32)__bfloat16_as_ushort(l3) << 16) | __bfloat16_as_ushort(l2);
    *(uint2*)(dh + (size_t)row * dst_ld + c4) = make_uint2(hA, hB);
    *(uint2*)(dl + (size_t)row * dst_ld + c4) = make_uint2(lA, lB);
}

// transpose+split: z==0 -> D [256][256]; z>=1 -> x2 batch z-1 [512][256]
__global__ void conv_trans_all(const float* __restrict__ Dm,
                               const float* __restrict__ x2,
                               bf16* __restrict__ bfb)
{
    __shared__ float t[32][33];
    const int z = blockIdx.z;
    const float* src; bf16 *dh, *dl;
    int R, C;
    if (z == 0) {
        if (blockIdx.y >= 8) return;
        src = Dm; dh = bfb + O_DTH; dl = bfb + O_DTL; R = 256; C = 256;
    } else {
        const int zz = z - 1;
        src = x2 + (size_t)zz * 512 * 256;
        dh = bfb + O_X2TH + (size_t)zz * 256 * 512;
        dl = bfb + O_X2TL + (size_t)zz * 256 * 512;
        R = 512; C = 256;
    }
    const int c0 = blockIdx.x * 32, r0 = blockIdx.y * 32;
    const int tx = threadIdx.x, ty = threadIdx.y;
#pragma unroll
    for (int i = 0; i < 4; i++)
        t[ty + i * 8][tx] = src[(size_t)(r0 + ty + i * 8) * C + c0 + tx];
    __syncthreads();
#pragma unroll
    for (int i = 0; i < 4; i++) {
        const float v = t[tx][ty + i * 8];
        bf16 h, l; split1(v, h, l);
        const size_t o = (size_t)(c0 + ty + i * 8) * R + r0 + tx;
        dh[o] = h; dl[o] = l;
    }
}

// ---------------------------------------------------------------------------
// bf16x3 HMMA GEMM. CTA tile 64x128, 256 threads = 8 warps (2m x 4n),
// warp tile 32x32 (same inner loop as R15). 3-stage cp.async, 2 CTAs/SM.
// EPI: 0=none, 1=relu, 2=mul E[r*eN+c], 3=add E[c]; OUT: 0 fp32, 1 split bf16.
// ---------------------------------------------------------------------------
#define LDR 40
#define MATA 5120                  // 64*40*2
#define MATB2 10240                // 128*40*2
#define STGB 30720                 // Ah+Al+Bh+Bl
#define GEMM_SMEM (3 * STGB)       // 92160

__device__ __forceinline__ void ldsm4(u32& r0, u32& r1, u32& r2, u32& r3, u32 a) {
    asm volatile("ldmatrix.sync.aligned.m8n8.x4.shared.b16 {%0,%1,%2,%3}, [%4];"
                 : "=r"(r0), "=r"(r1), "=r"(r2), "=r"(r3) : "r"(a));
}
__device__ __forceinline__ void mma_bf16(float* c, const u32* a, const u32* b) {
    asm volatile(
        "mma.sync.aligned.m16n8k16.row.col.f32.bf16.bf16.f32 "
        "{%0,%1,%2,%3}, {%4,%5,%6,%7}, {%8,%9}, {%0,%1,%2,%3};"
        : "+f"(c[0]), "+f"(c[1]), "+f"(c[2]), "+f"(c[3])
        : "r"(a[0]), "r"(a[1]), "r"(a[2]), "r"(a[3]), "r"(b[0]), "r"(b[1]));
}

template<int EPI, int OUT>
__global__ void __launch_bounds__(256, 2) gemm_bb(
    const bf16* __restrict__ Ah, const bf16* __restrict__ Al,
    const bf16* __restrict__ Bh, const bf16* __restrict__ Bl,
    float* __restrict__ C, bf16* __restrict__ Ch, bf16* __restrict__ Cl,
    int K, int lda, int ldb, int ldc,
    long long sA, long long sB, long long sC,
    const float* __restrict__ E, int eN)
{
    extern __shared__ __align__(16) unsigned char sm[];
    const long long z = blockIdx.z;
    Ah += z * sA; Al += z * sA;
    Bh += z * sB; Bl += z * sB;
    if (OUT == 0) C += z * sC; else { Ch += z * sC; Cl += z * sC; }

    const int tid = threadIdx.x;
    const int wid = tid >> 5, lane = tid & 31;
    const int wm = wid >> 2, wn = wid & 3;       // 2m x 4n
    const int m0 = blockIdx.y * 64, n0 = blockIdx.x * 128;

    const int row = tid >> 2;        // 0..63
    const int ko = (tid & 3) * 8;
    const u32 smb = saddr(sm);
    const u32 soff = (u32)(row * LDR + ko) * 2;

    const int q = lane >> 3, lr = lane & 7;
    const int a_t = (lr + (q & 1) * 8) * LDR + (q >> 1) * 8;
    const int b_t = (lr + (q >> 1) * 8) * LDR + (q & 1) * 8;

    float acc[2][4][4];
#pragma unroll
    for (int mt = 0; mt < 2; mt++)
#pragma unroll
        for (int nt = 0; nt < 4; nt++)
#pragma unroll
            for (int e = 0; e < 4; e++) acc[mt][nt][e] = 0.f;

    const int nch = K >> 5;

#define ISSUE(c, st) do {                                                    \
        const u32 sb_ = smb + (u32)(st) * STGB;                              \
        const size_t ao_ = (size_t)(m0 + row) * lda + (c) * 32 + ko;         \
        const size_t b1_ = (size_t)(n0 + row) * ldb + (c) * 32 + ko;         \
        const size_t b2_ = (size_t)(n0 + row + 64) * ldb + (c) * 32 + ko;    \
        cp16(sb_ + soff,                     Ah + ao_);                      \
        cp16(sb_ + MATA + soff,              Al + ao_);                      \
        cp16(sb_ + 2 * MATA + soff,          Bh + b1_);                      \
        cp16(sb_ + 2 * MATA + MATB2 + soff,  Bl + b1_);                      \
        cp16(sb_ + 2 * MATA + soff + 64 * LDR * 2,          Bh + b2_);       \
        cp16(sb_ + 2 * MATA + MATB2 + soff + 64 * LDR * 2,  Bl + b2_);       \
        asm volatile("cp.async.commit_group;" ::: "memory");                 \
    } while (0)

    ISSUE(0, 0); ISSUE(1, 1);
    int stage = 0;

    for (int c = 0; c < nch; c++) {
        asm volatile("cp.async.wait_group 1;" ::: "memory");
        __syncthreads();
        if (c + 2 < nch) {
            int st = stage + 2; if (st >= 3) st -= 3;
            ISSUE(c + 2, st);
        }

        const u32 base = smb + (u32)stage * STGB;
#pragma unroll
        for (int ks = 0; ks < 32; ks += 16) {
            u32 ah[2][4], al[2][4], bh[4][2], bl[4][2];
#pragma unroll
            for (int mt = 0; mt < 2; mt++) {
                const u32 off = (u32)(a_t + (wm * 32 + mt * 16) * LDR + ks) * 2;
                ldsm4(ah[mt][0], ah[mt][1], ah[mt][2], ah[mt][3], base + off);
                ldsm4(al[mt][0], al[mt][1], al[mt][2], al[mt][3], base + off + MATA);
            }
#pragma unroll
            for (int np = 0; np < 2; np++) {
                const u32 off = (u32)(b_t + (wn * 32 + np * 16) * LDR + ks) * 2;
                u32 t0, t1, t2, t3;
                ldsm4(t0, t1, t2, t3, base + off + 2 * MATA);
                bh[2 * np][0] = t0; bh[2 * np][1] = t1;
                bh[2 * np + 1][0] = t2; bh[2 * np + 1][1] = t3;
                ldsm4(t0, t1, t2, t3, base + off + 2 * MATA + MATB2);
                bl[2 * np][0] = t0; bl[2 * np][1] = t1;
                bl[2 * np + 1][0] = t2; bl[2 * np + 1][1] = t3;
            }
#pragma unroll
            for (int mt = 0; mt < 2; mt++)
#pragma unroll
                for (int nt = 0; nt < 4; nt++) {
                    mma_bf16(acc[mt][nt], ah[mt], bh[nt]);
                    mma_bf16(acc[mt][nt], ah[mt], bl[nt]);
                    mma_bf16(acc[mt][nt], al[mt], bh[nt]);
                }
        }
        if (++stage == 3) stage = 0;
    }
#undef ISSUE

    const int rbase = m0 + wm * 32 + (lane >> 2);
    const int cbase = n0 + wn * 32 + (lane & 3) * 2;
#pragma unroll
    for (int mt = 0; mt < 2; mt++) {
#pragma unroll
        for (int nt = 0; nt < 4; nt++) {
            const int col = cbase + nt * 8;
#pragma unroll
            for (int half = 0; half < 2; half++) {
                const int r = rbase + mt * 16 + half * 8;
                float v0 = acc[mt][nt][half * 2];
                float v1 = acc[mt][nt][half * 2 + 1];
                if (EPI == 1) { v0 = fmaxf(v0, 0.f); v1 = fmaxf(v1, 0.f); }
                else if (EPI == 2) {
                    const float2 e = *(const float2*)&E[(size_t)r * eN + col];
                    v0 *= e.x; v1 *= e.y;
                } else if (EPI == 3) {
                    const float2 e = *(const float2*)&E[col];
                    v0 += e.x; v1 += e.y;
                }
                if (OUT == 0) {
                    *(float2*)&C[(size_t)r * ldc + col] = make_float2(v0, v1);
                } else {
                    bf16 h0, l0, h1, l1;
                    split1(v0, h0, l0); split1(v1, h1, l1);
                    *(u32*)&Ch[(size_t)r * ldc + col] =
                        ((u32)__bfloat16_as_ushort(h1) << 16) | __bfloat16_as_ushort(h0);
                    *(u32*)&Cl[(size_t)r * ldc + col] =
                        ((u32)__bfloat16_as_ushort(l1) << 16) | __bfloat16_as_ushort(l0);
                }
            }
        }
    }
}

// ---------------------------------------------------------------------------
__global__ void softmax_dim1_kernel(const float* __restrict__ Mm,
                                    bf16* __restrict__ mh, bf16* __restrict__ ml)
{
    const int idx = blockIdx.x * 256 + threadIdx.x;
    const int b = idx >> 9, c = idx & 511;
    const float* p = Mm + (size_t)b * (512 * 512) + c;

    float mx = -1e30f, s = 0.f;
#pragma unroll 8
    for (int i = 0; i < 512; i++) {
        const float v = p[(size_t)i * 512];
        const float nm = fmaxf(mx, v);
        s = s * __expf(mx - nm) + __expf(v - nm);
        mx = nm;
    }
    const float inv = 1.f / s;
    bf16* ph = mh + (size_t)b * (512 * 512) + c;
    bf16* pl = ml + (size_t)b * (512 * 512) + c;
#pragma unroll 8
    for (int i = 0; i < 512; i++) {
        const float v = __expf(p[(size_t)i * 512] - mx) * inv;
        bf16 h, l; split1(v, h, l);
        ph[(size_t)i * 512] = h;
        pl[(size_t)i * 512] = l;
    }
}

// ---------------------------------------------------------------------------
// GRU v4 (FROZEN — measured best): 16 clusters of 8 CTAs, st.async sync.
// ---------------------------------------------------------------------------
__device__ __forceinline__ u64 pk2(float a, float b) {
    u64 r; asm("mov.b64 %0, {%1, %2};" : "=l"(r) : "f"(a), "f"(b)); return r;
}
__device__ __forceinline__ void fma2(u64& d, u64 a, u64 b) {
    asm("fma.rn.f32x2 %0, %1, %2, %0;" : "+l"(d) : "l"(a), "l"(b));
}
__device__ __forceinline__ u64 add2(u64 a, u64 b) {
    u64 d; asm("add.rn.f32x2 %0, %1, %2;" : "=l"(d) : "l"(a), "l"(b)); return d;
}
__device__ __forceinline__ float2 unpk(u64 v) {
    float2 f; asm("mov.b64 {%0, %1}, %2;" : "=f"(f.x), "=f"(f.y) : "l"(v)); return f;
}

template<int CUR, bool DO_WAIT>
__device__ __forceinline__ void gru_step(
    int t, int tid, int kq, int b0, int gi, int b_l, int hl2,
    const u64 (&w2reg)[3][16],
    u64 (&hbuf)[2][2][128], u64 (&parts)[3][2][8][32],
    u32 mb_cur, u32 parity,
    const u32 (&dd)[8], const u32 (&dm)[8],
    float br, float bz, float bn,
    float& xr_c, float& xz_c, float& xn_c,
    const float* __restrict__ xp, float* __restrict__ out)
{
    float xr_n = 0.f, xz_n = 0.f, xn_n = 0.f;
    if (tid < 64) {
        const int tn = (t + 1 < 512) ? t + 1 : 511;
        const float* p = xp + ((size_t)(b0 + b_l) * 512 + tn) * 768 + gi * 32 + hl2;
        xr_n = __ldg(p); xz_n = __ldg(p + 256); xn_n = __ldg(p + 512);
    }

    if (DO_WAIT) {
        mbar_wait(mb_cur, parity);
        if (tid == 0)
            asm volatile("mbarrier.arrive.expect_tx.shared.b64 _, [%0], %1;"
                         :: "r"(mb_cur), "r"(2048u) : "memory");
    }

    const int h_l = tid & 31;
    const u64* h0p = &hbuf[CUR][0][kq * 16];
    const u64* h1p = &hbuf[CUR][1][kq * 16];
    u64 a00 = 0, a01 = 0, a10 = 0, a11 = 0, a20 = 0, a21 = 0;
#pragma unroll
    for (int kp = 0; kp < 16; kp++) {
        const u64 ha = h0p[kp], hb = h1p[kp];
        fma2(a00, ha, w2reg[0][kp]); fma2(a01, hb, w2reg[0][kp]);
        fma2(a10, ha, w2reg[1][kp]); fma2(a11, hb, w2reg[1][kp]);
        fma2(a20, ha, w2reg[2][kp]); fma2(a21, hb, w2reg[2][kp]);
    }
    parts[0][0][kq][h_l] = a00; parts[0][1][kq][h_l] = a01;
    parts[1][0][kq][h_l] = a10; parts[1][1][kq][h_l] = a11;
    parts[2][0][kq][h_l] = a20; parts[2][1][kq][h_l] = a21;
    __syncthreads();

    if (tid < 64) {
        u64 sr = parts[0][b_l][0][hl2];
        u64 sz = parts[1][b_l][0][hl2];
        u64 sn = parts[2][b_l][0][hl2];
#pragma unroll
        for (int qq = 1; qq < 8; qq++) {
            sr = add2(sr, parts[0][b_l][qq][hl2]);
            sz = add2(sz, parts[1][b_l][qq][hl2]);
            sn = add2(sn, parts[2][b_l][qq][hl2]);
        }
        const float2 fr = unpk(sr), fz = unpk(sz), fn = unpk(sn);
        const float hr = fr.x + fr.y + br;
        const float hz = fz.x + fz.y + bz;
        const float hn = fn.x + fn.y + bn;

        const float r = 1.f / (1.f + __expf(-(xr_c + hr)));
        const float z = 1.f / (1.f + __expf(-(xz_c + hz)));
        const float n = tanhf(xn_c + r * hn);
        const float hp = ((const float*)&hbuf[CUR][b_l][0])[gi * 32 + hl2];
        const float hnew = (1.f - z) * n + z * hp;
        const u32 hbits = __float_as_uint(hnew);

#pragma unroll
        for (int rk = 0; rk < 8; rk++)
            asm volatile(
                "st.async.shared::cluster.mbarrier::complete_tx::bytes.b32 [%0], %1, [%2];"
                :: "r"(dd[rk]), "r"(hbits), "r"(dm[rk]) : "memory");

        out[((size_t)(b0 + b_l) * 512 + t) * 256 + gi * 32 + hl2] = hnew;
    }
    xr_c = xr_n; xz_c = xz_n; xn_c = xn_n;
}

__global__ void __launch_bounds__(256, 1) __cluster_dims__(8, 1, 1)
gru_kernel(const float* __restrict__ xp,
           const float* __restrict__ whh,
           const float* __restrict__ bhh,
           float* __restrict__ out)
{
    __shared__ __align__(16) u64 hbuf[2][2][128];
    __shared__ __align__(16) u64 parts[3][2][8][32];
    __shared__ __align__(8)  u64 mbars[2];

    const int tid = threadIdx.x;
    u32 gi; asm("mov.u32 %0, %%cluster_ctarank;" : "=r"(gi));
    const int b0 = (blockIdx.x >> 3) * 2;
    const int h_l = tid & 31;
    const int kq  = tid >> 5;
    const int hg  = gi * 32 + h_l;

    u64 w2reg[3][16];
#pragma unroll
    for (int g = 0; g < 3; g++) {
        const float* wr = whh + (size_t)(g * 256 + hg) * 256 + kq * 32;
#pragma unroll
        for (int kp = 0; kp < 16; kp += 2) {
            float4 v = __ldg((const float4*)(wr + kp * 2));
            w2reg[g][kp]     = pk2(v.x, v.y);
            w2reg[g][kp + 1] = pk2(v.z, v.w);
        }
    }

    const u32 mb0 = saddr(&mbars[0]);
    const u32 mb1 = saddr(&mbars[1]);
    if (tid == 0) {
        asm volatile("mbarrier.init.shared.b64 [%0], 1;" :: "r"(mb0) : "memory");
        asm volatile("mbarrier.init.shared.b64 [%0], 1;" :: "r"(mb1) : "memory");
        asm volatile("fence.proxy.async.shared::cta;" ::: "memory");
        asm volatile("mbarrier.arrive.expect_tx.shared.b64 _, [%0], %1;"
                     :: "r"(mb0), "r"(2048u) : "memory");
        asm volatile("mbarrier.arrive.expect_tx.shared.b64 _, [%0], %1;"
                     :: "r"(mb1), "r"(2048u) : "memory");
    }
    ((u64*)hbuf)[tid] = 0ull;
    ((u64*)hbuf)[tid + 256] = 0ull;
    __syncthreads();
    asm volatile("barrier.cluster.arrive.aligned;" ::: "memory");
    asm volatile("barrier.cluster.wait.aligned;" ::: "memory");

    float br = 0.f, bz = 0.f, bn = 0.f;
    int b_l = 0, hl2 = 0;
    u32 dd0[8], dd1[8], dm0[8], dm1[8];
#pragma unroll
    for (int rk = 0; rk < 8; rk++) { dd0[rk] = dd1[rk] = dm0[rk] = dm1[rk] = 0u; }
    if (tid < 64) {
        b_l = tid >> 5; hl2 = tid & 31;
        const int hgf = gi * 32 + hl2;
        br = __ldg(&bhh[hgf]);
        bz = __ldg(&bhh[256 + hgf]);
        bn = __ldg(&bhh[512 + hgf]);
        const u32 la0 = saddr(&((float*)&hbuf[0][b_l][0])[hgf]);
        const u32 la1 = saddr(&((float*)&hbuf[1][b_l][0])[hgf]);
#pragma unroll
        for (int rk = 0; rk < 8; rk++) {
            asm("mapa.shared::cluster.u32 %0, %1, %2;" : "=r"(dd0[rk]) : "r"(la0), "r"(rk));
            asm("mapa.shared::cluster.u32 %0, %1, %2;" : "=r"(dd1[rk]) : "r"(la1), "r"(rk));
            asm("mapa.shared::cluster.u32 %0, %1, %2;" : "=r"(dm0[rk]) : "r"(mb0), "r"(rk));
            asm("mapa.shared::cluster.u32 %0, %1, %2;" : "=r"(dm1[rk]) : "r"(mb1), "r"(rk));
        }
    }

    float xr_c = 0.f, xz_c = 0.f, xn_c = 0.f;
    if (tid < 64) {
        const float* p = xp + ((size_t)(b0 + b_l) * 512) * 768 + gi * 32 + hl2;
        xr_c = __ldg(p); xz_c = __ldg(p + 256); xn_c = __ldg(p + 512);
    }

    u32 p0 = 0, p1 = 0;
    gru_step<0, false>(0, tid, kq, b0, gi, b_l, hl2, w2reg, hbuf, parts,
                       mb0, 0u, dd1, dm1, br, bz, bn, xr_c, xz_c, xn_c, xp, out);
    for (int t = 1; t < 511; t += 2) {
        gru_step<1, true>(t, tid, kq, b0, gi, b_l, hl2, w2reg, hbuf, parts,
                          mb1, p1, dd0, dm0, br, bz, bn, xr_c, xz_c, xn_c, xp, out);
        p1 ^= 1u;
        gru_step<0, true>(t + 1, tid, kq, b0, gi, b_l, hl2, w2reg, hbuf, parts,
                          mb0, p0, dd1, dm1, br, bz, bn, xr_c, xz_c, xn_c, xp, out);
        p0 ^= 1u;
    }
    gru_step<1, true>(511, tid, kq, b0, gi, b_l, hl2, w2reg, hbuf, parts,
                      mb1, p1, dd0, dm0, br, bz, bn, xr_c, xz_c, xn_c, xp, out);
    mbar_wait(mb0, p0);
}

// ---------------------------------------------------------------------------
extern "C" void kernel_launch(void* const* d_in, const int* in_sizes, int n_in,
                              void* d_out, int out_size)
{
    const float* x1  = (const float*)d_in[0];
    const float* x2  = (const float*)d_in[1];
    const float* w1  = (const float*)d_in[2];
    const float* w2  = (const float*)d_in[3];
    const float* Dm  = (const float*)d_in[4];
    const float* Wm  = (const float*)d_in[5];
    const float* wih = (const float*)d_in[6];
    const float* whh = (const float*)d_in[7];
    const float* bih = (const float*)d_in[8];
    const float* bhh = (const float*)d_in[9];
    float* out = (float*)d_out;

    float* f32 = nullptr; bf16* bf = nullptr;
    cudaGetSymbolAddress((void**)&f32, g_f32);
    cudaGetSymbolAddress((void**)&bf, g_bf);

    float* MM = f32 + F_MM;
    float* XP = f32 + F_XP;

    cudaFuncSetAttribute(gemm_bb<1, 1>, cudaFuncAttributeMaxDynamicSharedMemorySize, GEMM_SMEM);
    cudaFuncSetAttribute(gemm_bb<0, 1>, cudaFuncAttributeMaxDynamicSharedMemorySize, GEMM_SMEM);
    cudaFuncSetAttribute(gemm_bb<2, 0>, cudaFuncAttributeMaxDynamicSharedMemorySize, GEMM_SMEM);
    cudaFuncSetAttribute(gemm_bb<3, 0>, cudaFuncAttributeMaxDynamicSharedMemorySize, GEMM_SMEM);

    // ---- conversions (2 launches) ----
    conv_split_all<<<dim3(4096, 5), 256>>>(x1, x2, w1, w2, wih, bf);
    conv_trans_all<<<dim3(8, 16, 33), dim3(32, 8)>>>(Dm, x2, bf);

    // ---- GEMMs (64x128 tiles) ----
    // t1 = relu(x1 @ w1^T)
    gemm_bb<1, 1><<<dim3(2, 256, 1), 256, GEMM_SMEM>>>(
        bf + O_GGH, bf + O_GGL, bf + O_W1H, bf + O_W1L,
        nullptr, bf + O_T1H, bf + O_T1L,
        256, 512, 256, 256, 0, 0, 0, nullptr, 0);
    // a2 = relu(x2 @ w2^T)
    gemm_bb<1, 1><<<dim3(2, 256, 1), 256, GEMM_SMEM>>>(
        bf + O_X2H, bf + O_X2L, bf + O_W2H, bf + O_W2L,
        nullptr, bf + O_A2H, bf + O_A2L,
        256, 256, 256, 256, 0, 0, 0, nullptr, 0);
    // a1 = t1 @ (D^T)^T
    gemm_bb<0, 1><<<dim3(2, 256, 1), 256, GEMM_SMEM>>>(
        bf + O_T1H, bf + O_T1L, bf + O_DTH, bf + O_DTL,
        nullptr, bf + O_A1H, bf + O_A1L,
        256, 256, 256, 256, 0, 0, 0, nullptr, 0);
    // M[b] = (a1[b] @ a2[b]^T) * W
    gemm_bb<2, 0><<<dim3(4, 8, 32), 256, GEMM_SMEM>>>(
        bf + O_A1H, bf + O_A1L, bf + O_A2H, bf + O_A2L,
        MM, nullptr, nullptr,
        256, 256, 256, 512,
        (long long)512 * 256, (long long)512 * 256, (long long)512 * 512, Wm, 512);
    // softmax over dim=1 -> M split
    softmax_dim1_kernel<<<64, 256>>>(MM, bf + O_MH, bf + O_ML);
    // ctx[b] = M[b] @ (x2t[b])^T -> GG right half (split)
    gemm_bb<0, 1><<<dim3(2, 8, 32), 256, GEMM_SMEM>>>(
        bf + O_MH, bf + O_ML, bf + O_X2TH, bf + O_X2TL,
        nullptr, bf + O_GGH + 256, bf + O_GGL + 256,
        512, 512, 512, 512,
        (long long)512 * 512, (long long)256 * 512, (long long)512 * 512,
        nullptr, 0);
    // xp = g @ wih^T + bih
    gemm_bb<3, 0><<<dim3(6, 256, 1), 256, GEMM_SMEM>>>(
        bf + O_GGH, bf + O_GGL, bf + O_WIHH, bf + O_WIHL,
        XP, nullptr, nullptr,
        512, 512, 512, 768, 0, 0, 0, bih, 0);
    // GRU v4 (frozen)
    gru_kernel<<<128, 256>>>(XP, whh, bhh, out);
}